// round 4
// baseline (speedup 1.0000x reference)
#include <cuda_runtime.h>

#define R 4096
#define F 256
#define K 8
#define CMIN 1e-6f
#define CMAX 1e6f

#define BM 64
#define BN 64
#define BK 16

// Scratch (static device globals — no runtime allocation)
__device__ float g_base[(size_t)R * (size_t)R];   // 64 MB: base[r,c]
__device__ float g_S[K * R];                      // softmax denominators
__device__ float g_rs[4 * R];                     // sx1 | n2x1 | sx2 | n2x2
__device__ float g_kp[4 * K];                     // a_k | b_k | ek_k | nw_k

// ---------------------------------------------------------------------------
// Per-k parameters: a = -2*mean, b = F*mean^2, ek = -1/(2*sigma^2),
// nw = softmax(1/sp^2) with max-subtraction (weights can be huge).
__global__ void params_kernel(const float* __restrict__ sig,
                              const float* __restrict__ mean,
                              const float* __restrict__ sp) {
    if (threadIdx.x == 0) {
        float w[K];
        float m = -3.4e38f;
        #pragma unroll
        for (int k = 0; k < K; k++) {
            float v = 1.0f / (sp[k] * sp[k]);
            w[k] = v;
            if (v > m) m = v;
        }
        float s = 0.0f;
        #pragma unroll
        for (int k = 0; k < K; k++) { w[k] = __expf(w[k] - m); s += w[k]; }
        float inv_s = 1.0f / s;
        #pragma unroll
        for (int k = 0; k < K; k++) {
            g_kp[k]         = -2.0f * mean[k];
            g_kp[K + k]     = (float)F * mean[k] * mean[k];
            g_kp[2 * K + k] = -1.0f / (2.0f * sig[k] * sig[k]);
            g_kp[3 * K + k] = w[k] * inv_s;
        }
    }
}

__global__ void zero_S_kernel() {
    int i = blockIdx.x * blockDim.x + threadIdx.x;
    if (i < K * R) g_S[i] = 0.0f;
}

// Row sums and squared norms of x1 and x2 (one warp per row).
__global__ void stats_kernel(const float* __restrict__ x1,
                             const float* __restrict__ x2) {
    int w = blockIdx.x * (blockDim.x >> 5) + (threadIdx.x >> 5);
    int lane = threadIdx.x & 31;
    if (w >= 2 * R) return;
    const float* x = (w < R) ? x1 : x2;
    int row = (w < R) ? w : (w - R);
    float s = 0.0f, q = 0.0f;
    #pragma unroll
    for (int i = 0; i < F / 32; i++) {
        float v = x[(size_t)row * F + lane + i * 32];
        s += v;
        q = fmaf(v, v, q);
    }
    #pragma unroll
    for (int o = 16; o > 0; o >>= 1) {
        s += __shfl_xor_sync(0xFFFFFFFFu, s, o);
        q += __shfl_xor_sync(0xFFFFFFFFu, q, o);
    }
    if (lane == 0) {
        int off = (w < R) ? 0 : 2 * R;
        g_rs[off + row]     = s;
        g_rs[off + R + row] = q;
    }
}

// ---------------------------------------------------------------------------
// Kernel A: tiled fp32 GEMM producing base[r,c]; fused epilogue computes
// exp(exp(-dist_k/(2 sigma_k^2))) sums per (k, row) into g_S, stores base.
__global__ void __launch_bounds__(256, 2)
kernelA(const float* __restrict__ x1, const float* __restrict__ x2) {
    __shared__ float As[BK][BM + 4];   // +4 pad keeps 16B alignment, kills conflicts
    __shared__ float Bs[BK][BN + 4];

    const int tid = threadIdx.x;
    const int tx = tid & 15;           // column group (lane % 16)
    const int ty = tid >> 4;           // row group
    const int r0 = blockIdx.y * BM;
    const int c0 = blockIdx.x * BN;

    // loaders: 64 rows x 16 floats per tile; each thread loads one float4
    const int lrow = tid >> 2;
    const int lf4  = (tid & 3) * 4;

    float acc[4][4];
    #pragma unroll
    for (int i = 0; i < 4; i++)
        #pragma unroll
        for (int j = 0; j < 4; j++) acc[i][j] = 0.0f;

    const float* ap = x1 + (size_t)(r0 + lrow) * F + lf4;
    const float* bp = x2 + (size_t)(c0 + lrow) * F + lf4;

    for (int k0 = 0; k0 < F; k0 += BK) {
        float4 av = *(const float4*)(ap + k0);
        float4 bv = *(const float4*)(bp + k0);
        __syncthreads();
        As[lf4 + 0][lrow] = av.x; As[lf4 + 1][lrow] = av.y;
        As[lf4 + 2][lrow] = av.z; As[lf4 + 3][lrow] = av.w;
        Bs[lf4 + 0][lrow] = bv.x; Bs[lf4 + 1][lrow] = bv.y;
        Bs[lf4 + 2][lrow] = bv.z; Bs[lf4 + 3][lrow] = bv.w;
        __syncthreads();
        #pragma unroll
        for (int kk = 0; kk < BK; kk++) {
            float4 a4 = *(const float4*)&As[kk][ty * 4];
            float4 b4 = *(const float4*)&Bs[kk][tx * 4];
            float ar[4] = {a4.x, a4.y, a4.z, a4.w};
            float br[4] = {b4.x, b4.y, b4.z, b4.w};
            #pragma unroll
            for (int i = 0; i < 4; i++)
                #pragma unroll
                for (int j = 0; j < 4; j++)
                    acc[i][j] = fmaf(ar[i], br[j], acc[i][j]);
        }
    }

    // ---- epilogue ----
    float ak[K], bk[K], ekc[K];
    #pragma unroll
    for (int k = 0; k < K; k++) {
        ak[k]  = g_kp[k];
        bk[k]  = g_kp[K + k];
        ekc[k] = g_kp[2 * K + k];
    }
    float sx1r[4], n21[4], sx2c[4], n22[4];
    #pragma unroll
    for (int i = 0; i < 4; i++) {
        int r = r0 + ty * 4 + i;
        sx1r[i] = g_rs[r];
        n21[i]  = g_rs[R + r];
    }
    #pragma unroll
    for (int j = 0; j < 4; j++) {
        int c = c0 + tx * 4 + j;
        sx2c[j] = g_rs[2 * R + c];
        n22[j]  = g_rs[3 * R + c];
    }

    float ssum[K][4];
    #pragma unroll
    for (int k = 0; k < K; k++)
        #pragma unroll
        for (int i = 0; i < 4; i++) ssum[k][i] = 0.0f;

    #pragma unroll
    for (int i = 0; i < 4; i++) {
        float4 bout;
        float* bo = (float*)&bout;
        #pragma unroll
        for (int j = 0; j < 4; j++) {
            float base = n21[i] + n22[j] - 2.0f * acc[i][j];
            float sv   = sx1r[i] - sx2c[j];
            bo[j] = base;
            #pragma unroll
            for (int k = 0; k < K; k++) {
                float dist = fmaf(ak[k], sv, base) + bk[k];
                dist = fminf(fmaxf(dist, CMIN), CMAX);
                float kv = __expf(dist * ekc[k]);   // in (0, 1]
                ssum[k][i] += __expf(kv);
            }
        }
        *(float4*)&g_base[(size_t)(r0 + ty * 4 + i) * R + c0 + tx * 4] = bout;
    }

    // reduce ssum across the 16 lanes that share the same rows (xor <= 8 stays
    // within each 16-lane half; the two halves of a warp hold different rows)
    #pragma unroll
    for (int k = 0; k < K; k++) {
        #pragma unroll
        for (int i = 0; i < 4; i++) {
            float v = ssum[k][i];
            v += __shfl_xor_sync(0xFFFFFFFFu, v, 1);
            v += __shfl_xor_sync(0xFFFFFFFFu, v, 2);
            v += __shfl_xor_sync(0xFFFFFFFFu, v, 4);
            v += __shfl_xor_sync(0xFFFFFFFFu, v, 8);
            if (tx == 0)
                atomicAdd(&g_S[k * R + r0 + ty * 4 + i], v);
        }
    }
}

// ---------------------------------------------------------------------------
// Kernel B: one block per row r; recompute kv from stored base, apply
// softmax normalization and weighted sum over k, write output.
__global__ void __launch_bounds__(256)
kernelB(float* __restrict__ out) {
    const int r = blockIdx.x;
    __shared__ float sak[K], sbk[K], sek[K], swk[K];
    if (threadIdx.x < K) {
        int k = threadIdx.x;
        sak[k] = g_kp[k];
        sbk[k] = g_kp[K + k];
        sek[k] = g_kp[2 * K + k];
        swk[k] = g_kp[3 * K + k] / g_S[k * R + r];
    }
    __syncthreads();

    float ak[K], bk[K], ekc[K], wk[K];
    #pragma unroll
    for (int k = 0; k < K; k++) {
        ak[k] = sak[k]; bk[k] = sbk[k]; ekc[k] = sek[k]; wk[k] = swk[k];
    }
    const float sx1r = g_rs[r];
    const float* baserow = g_base + (size_t)r * R;
    float* outrow = out + (size_t)r * R;

    #pragma unroll
    for (int it = 0; it < R / (256 * 4); it++) {
        int c = (it * 256 + threadIdx.x) * 4;
        float4 b4 = *(const float4*)(baserow + c);
        float4 s4 = *(const float4*)(g_rs + 2 * R + c);
        float bb[4] = {b4.x, b4.y, b4.z, b4.w};
        float ss[4] = {sx1r - s4.x, sx1r - s4.y, sx1r - s4.z, sx1r - s4.w};
        float o[4] = {0.0f, 0.0f, 0.0f, 0.0f};
        #pragma unroll
        for (int j = 0; j < 4; j++) {
            #pragma unroll
            for (int k = 0; k < K; k++) {
                float dist = fmaf(ak[k], ss[j], bb[j]) + bk[k];
                dist = fminf(fmaxf(dist, CMIN), CMAX);
                float kv = __expf(dist * ekc[k]);
                o[j] = fmaf(__expf(kv), wk[k], o[j]);
            }
        }
        float4 ov = {o[0], o[1], o[2], o[3]};
        *(float4*)(outrow + c) = ov;
    }
}

// ---------------------------------------------------------------------------
extern "C" void kernel_launch(void* const* d_in, const int* in_sizes, int n_in,
                              void* d_out, int out_size) {
    const float* x1   = (const float*)d_in[0];  // [R, F]
    const float* x2   = (const float*)d_in[1];  // [R, F]
    const float* sig  = (const float*)d_in[2];  // [K]
    const float* mean = (const float*)d_in[3];  // [K]
    const float* sp   = (const float*)d_in[4];  // [K]
    float* out = (float*)d_out;                 // [R, R]

    params_kernel<<<1, 32>>>(sig, mean, sp);
    zero_S_kernel<<<(K * R + 255) / 256, 256>>>();
    stats_kernel<<<(2 * R) / 8, 256>>>(x1, x2);

    dim3 gridA(R / BN, R / BM);
    kernelA<<<gridA, 256>>>(x1, x2);

    kernelB<<<R, 256>>>(out);
}

// round 5
// speedup vs baseline: 1.1854x; 1.1854x over previous
#include <cuda_runtime.h>

#define R 4096
#define F 256
#define K 8
#define CMIN 1e-6f
#define CMAX 1e6f
#define L2E 1.4426950408889634f

#define BM 128
#define BN 128
#define BK 8

// Scratch (static device globals — no runtime allocation)
__device__ __align__(16) float g_base[(size_t)R * (size_t)R];  // 64 MB
__device__ __align__(16) float g_S[K * R];                     // softmax denominators
__device__ __align__(16) float g_rs[4 * R];                    // sx1 | n2x1 | sx2 | n2x2
__device__ __align__(16) float g_kp[6 * K];   // akt | bkt | ekc2 | lo | hi | nw

__device__ __forceinline__ float ex2f(float x) {
    float y;
    asm("ex2.approx.ftz.f32 %0, %1;" : "=f"(y) : "f"(x));
    return y;
}

// ---------------------------------------------------------------------------
// Folded per-k constants. dist = base + ak*sv + bk with ak=-2*mean, bk=F*mean^2.
// arg(=log2 of kv) = dist * ekc2, ekc2 = -log2e/(2 sigma^2) < 0.
// arg = fma(base, ekc2, fma(sv, akt, bkt)), akt = ak*ekc2, bkt = bk*ekc2.
// clip(dist,[CMIN,CMAX]) <=> clamp(arg,[CMAX*ekc2, CMIN*ekc2]).
__global__ void params_kernel(const float* __restrict__ sig,
                              const float* __restrict__ mean,
                              const float* __restrict__ sp) {
    if (threadIdx.x == 0) {
        float w[K];
        float m = -3.4e38f;
        #pragma unroll
        for (int k = 0; k < K; k++) {
            float v = 1.0f / (sp[k] * sp[k]);
            w[k] = v;
            if (v > m) m = v;
        }
        float s = 0.0f;
        #pragma unroll
        for (int k = 0; k < K; k++) { w[k] = __expf(w[k] - m); s += w[k]; }
        float inv_s = 1.0f / s;
        #pragma unroll
        for (int k = 0; k < K; k++) {
            float ekc2 = -L2E / (2.0f * sig[k] * sig[k]);
            float ak   = -2.0f * mean[k];
            float bk   = (float)F * mean[k] * mean[k];
            g_kp[k]         = ak * ekc2;      // akt
            g_kp[K + k]     = bk * ekc2;      // bkt
            g_kp[2 * K + k] = ekc2;
            g_kp[3 * K + k] = CMAX * ekc2;    // lo
            g_kp[4 * K + k] = CMIN * ekc2;    // hi
            g_kp[5 * K + k] = w[k] * inv_s;   // normalized weight
        }
    }
}

__global__ void zero_S_kernel() {
    int i = blockIdx.x * blockDim.x + threadIdx.x;
    if (i < K * R) g_S[i] = 0.0f;
}

// Row sums and squared norms of x1 and x2 (one warp per row).
__global__ void stats_kernel(const float* __restrict__ x1,
                             const float* __restrict__ x2) {
    int w = blockIdx.x * (blockDim.x >> 5) + (threadIdx.x >> 5);
    int lane = threadIdx.x & 31;
    if (w >= 2 * R) return;
    const float* x = (w < R) ? x1 : x2;
    int row = (w < R) ? w : (w - R);
    float s = 0.0f, q = 0.0f;
    #pragma unroll
    for (int i = 0; i < F / 32; i++) {
        float v = x[(size_t)row * F + lane + i * 32];
        s += v;
        q = fmaf(v, v, q);
    }
    #pragma unroll
    for (int o = 16; o > 0; o >>= 1) {
        s += __shfl_xor_sync(0xFFFFFFFFu, s, o);
        q += __shfl_xor_sync(0xFFFFFFFFu, q, o);
    }
    if (lane == 0) {
        int off = (w < R) ? 0 : 2 * R;
        g_rs[off + row]     = s;
        g_rs[off + R + row] = q;
    }
}

// ---------------------------------------------------------------------------
// Kernel A: 128x128x8 fp32 GEMM tile, 8x8 microtile; epilogue stores base
// and accumulates S[k,r] = sum_c exp(exp2(arg)) via shuffles + atomics.
__global__ void __launch_bounds__(256, 2)
kernelA(const float* __restrict__ x1, const float* __restrict__ x2) {
    __shared__ float As[BK][BM + 4];
    __shared__ float Bs[BK][BN + 4];
    __shared__ float skp[6 * K];

    const int tid = threadIdx.x;
    if (tid < 6 * K) skp[tid] = g_kp[tid];

    const int tx = tid & 15;          // 16 column groups
    const int ty = tid >> 4;          // 16 row groups
    const int r0 = blockIdx.y * BM;
    const int c0 = blockIdx.x * BN;

    // loader: each thread one float4 of A and of B per k-tile
    const int lrow = tid >> 1;        // 0..127
    const int lc4  = (tid & 1) * 4;   // 0 or 4

    float acc[8][8];
    #pragma unroll
    for (int i = 0; i < 8; i++)
        #pragma unroll
        for (int j = 0; j < 8; j++) acc[i][j] = 0.0f;

    const float* ap = x1 + (size_t)(r0 + lrow) * F + lc4;
    const float* bp = x2 + (size_t)(c0 + lrow) * F + lc4;

    float4 apre = *(const float4*)ap;
    float4 bpre = *(const float4*)bp;

    for (int k0 = 0; k0 < F; k0 += BK) {
        __syncthreads();
        As[lc4 + 0][lrow] = apre.x; As[lc4 + 1][lrow] = apre.y;
        As[lc4 + 2][lrow] = apre.z; As[lc4 + 3][lrow] = apre.w;
        Bs[lc4 + 0][lrow] = bpre.x; Bs[lc4 + 1][lrow] = bpre.y;
        Bs[lc4 + 2][lrow] = bpre.z; Bs[lc4 + 3][lrow] = bpre.w;
        __syncthreads();
        if (k0 + BK < F) {
            apre = *(const float4*)(ap + k0 + BK);
            bpre = *(const float4*)(bp + k0 + BK);
        }
        #pragma unroll
        for (int kk = 0; kk < BK; kk++) {
            float4 a0 = *(const float4*)&As[kk][ty * 8];
            float4 a1 = *(const float4*)&As[kk][ty * 8 + 4];
            float4 b0 = *(const float4*)&Bs[kk][tx * 8];
            float4 b1 = *(const float4*)&Bs[kk][tx * 8 + 4];
            float ar[8] = {a0.x, a0.y, a0.z, a0.w, a1.x, a1.y, a1.z, a1.w};
            float br[8] = {b0.x, b0.y, b0.z, b0.w, b1.x, b1.y, b1.z, b1.w};
            #pragma unroll
            for (int i = 0; i < 8; i++)
                #pragma unroll
                for (int j = 0; j < 8; j++)
                    acc[i][j] = fmaf(ar[i], br[j], acc[i][j]);
        }
    }

    // ---- epilogue ----
    const int rbase = r0 + ty * 8;
    const int cbase = c0 + tx * 8;

    // squared norms -> transform acc into base, store to g_base
    {
        float4 n21a = *(const float4*)&g_rs[R + rbase];
        float4 n21b = *(const float4*)&g_rs[R + rbase + 4];
        float4 n22a = *(const float4*)&g_rs[3 * R + cbase];
        float4 n22b = *(const float4*)&g_rs[3 * R + cbase + 4];
        float n21[8] = {n21a.x, n21a.y, n21a.z, n21a.w, n21b.x, n21b.y, n21b.z, n21b.w};
        float n22[8] = {n22a.x, n22a.y, n22a.z, n22a.w, n22b.x, n22b.y, n22b.z, n22b.w};
        #pragma unroll
        for (int i = 0; i < 8; i++) {
            #pragma unroll
            for (int j = 0; j < 8; j++)
                acc[i][j] = n21[i] + n22[j] - 2.0f * acc[i][j];
            float* dst = &g_base[(size_t)(rbase + i) * R + cbase];
            float4 o0 = {acc[i][0], acc[i][1], acc[i][2], acc[i][3]};
            float4 o1 = {acc[i][4], acc[i][5], acc[i][6], acc[i][7]};
            *(float4*)dst = o0;
            *(float4*)(dst + 4) = o1;
        }
    }

    // row/col sums
    float4 s1a = *(const float4*)&g_rs[rbase];
    float4 s1b = *(const float4*)&g_rs[rbase + 4];
    float4 s2a = *(const float4*)&g_rs[2 * R + cbase];
    float4 s2b = *(const float4*)&g_rs[2 * R + cbase + 4];
    float sx1r[8] = {s1a.x, s1a.y, s1a.z, s1a.w, s1b.x, s1b.y, s1b.z, s1b.w};
    float sx2c[8] = {s2a.x, s2a.y, s2a.z, s2a.w, s2b.x, s2b.y, s2b.z, s2b.w};

    #pragma unroll
    for (int k = 0; k < K; k++) {
        const float akt  = skp[k];
        const float bkt  = skp[K + k];
        const float ekc2 = skp[2 * K + k];
        const float lo   = skp[3 * K + k];
        const float hi   = skp[4 * K + k];
        float pi[8], qj[8];
        #pragma unroll
        for (int i = 0; i < 8; i++) pi[i] = fmaf(sx1r[i], akt, bkt);
        #pragma unroll
        for (int j = 0; j < 8; j++) qj[j] = sx2c[j] * akt;

        float ss[8];
        #pragma unroll
        for (int i = 0; i < 8; i++) ss[i] = 0.0f;

        #pragma unroll
        for (int i = 0; i < 8; i++) {
            #pragma unroll
            for (int j = 0; j < 8; j++) {
                float arg = fmaf(acc[i][j], ekc2, pi[i] - qj[j]);
                arg = fminf(fmaxf(arg, lo), hi);
                float kv = ex2f(arg);            // = exp(-dist/(2 sigma^2)) in (0,1]
                ss[i] += ex2f(kv * L2E);         // = exp(kv)
            }
        }
        // reduce across the 16 lanes sharing the same rows (xor <= 8 stays
        // within each 16-lane half of the warp)
        #pragma unroll
        for (int i = 0; i < 8; i++) {
            float v = ss[i];
            v += __shfl_xor_sync(0xFFFFFFFFu, v, 1);
            v += __shfl_xor_sync(0xFFFFFFFFu, v, 2);
            v += __shfl_xor_sync(0xFFFFFFFFu, v, 4);
            v += __shfl_xor_sync(0xFFFFFFFFu, v, 8);
            if (tx == 0) atomicAdd(&g_S[k * R + rbase + i], v);
        }
    }
}

// ---------------------------------------------------------------------------
// Kernel B: one block per row r; recompute kv from stored base, normalize,
// weighted sum over k, write output.
__global__ void __launch_bounds__(256)
kernelB(float* __restrict__ out) {
    const int r = blockIdx.x;
    __shared__ float sa[K], se[K], slo[K], shi[K], sw[K], sp_[K];
    if (threadIdx.x < K) {
        int k = threadIdx.x;
        float akt = g_kp[k];
        float bkt = g_kp[K + k];
        float sx1r = g_rs[r];
        sa[k]  = akt;
        se[k]  = g_kp[2 * K + k];
        slo[k] = g_kp[3 * K + k];
        shi[k] = g_kp[4 * K + k];
        sw[k]  = g_kp[5 * K + k] / g_S[k * R + r];
        sp_[k] = fmaf(sx1r, akt, bkt);   // pi for this row
    }
    __syncthreads();

    float akt[K], ekc2[K], lo[K], hi[K], wk[K], pr[K];
    #pragma unroll
    for (int k = 0; k < K; k++) {
        akt[k] = sa[k]; ekc2[k] = se[k]; lo[k] = slo[k];
        hi[k] = shi[k]; wk[k] = sw[k];   pr[k] = sp_[k];
    }
    const float* baserow = g_base + (size_t)r * R;
    float* outrow = out + (size_t)r * R;

    #pragma unroll
    for (int it = 0; it < R / (256 * 4); it++) {
        int c = (it * 256 + threadIdx.x) * 4;
        float4 b4 = *(const float4*)(baserow + c);
        float4 s4 = *(const float4*)(g_rs + 2 * R + c);
        float bb[4] = {b4.x, b4.y, b4.z, b4.w};
        float cc[4] = {s4.x, s4.y, s4.z, s4.w};
        float o[4] = {0.0f, 0.0f, 0.0f, 0.0f};
        #pragma unroll
        for (int j = 0; j < 4; j++) {
            #pragma unroll
            for (int k = 0; k < K; k++) {
                float q = cc[j] * akt[k];
                float arg = fmaf(bb[j], ekc2[k], pr[k] - q);
                arg = fminf(fmaxf(arg, lo[k]), hi[k]);
                float kv = ex2f(arg);
                o[j] = fmaf(ex2f(kv * L2E), wk[k], o[j]);
            }
        }
        float4 ov = {o[0], o[1], o[2], o[3]};
        *(float4*)(outrow + c) = ov;
    }
}

// ---------------------------------------------------------------------------
extern "C" void kernel_launch(void* const* d_in, const int* in_sizes, int n_in,
                              void* d_out, int out_size) {
    const float* x1   = (const float*)d_in[0];  // [R, F]
    const float* x2   = (const float*)d_in[1];  // [R, F]
    const float* sig  = (const float*)d_in[2];  // [K]
    const float* mean = (const float*)d_in[3];  // [K]
    const float* sp   = (const float*)d_in[4];  // [K]
    float* out = (float*)d_out;                 // [R, R]

    params_kernel<<<1, 32>>>(sig, mean, sp);
    zero_S_kernel<<<(K * R + 255) / 256, 256>>>();
    stats_kernel<<<(2 * R) / 8, 256>>>(x1, x2);

    dim3 gridA(R / BN, R / BM);
    kernelA<<<gridA, 256>>>(x1, x2);

    kernelB<<<R, 256>>>(out);
}

// round 6
// speedup vs baseline: 1.2003x; 1.0125x over previous
#include <cuda_runtime.h>

#define R 4096
#define F 256
#define K 8
#define CMIN 1e-6f
#define CMAX 1e6f
#define L2E 1.4426950408889634f

#define BM 128
#define BN 128
#define BK 16

// Scratch (static device globals — no runtime allocation)
__device__ __align__(16) float g_base[(size_t)R * (size_t)R];  // 64 MB
__device__ __align__(16) float g_S[K * R];                     // softmax denominators
__device__ __align__(16) float g_rs[4 * R];                    // sx1 | n2x1 | sx2 | n2x2
__device__ __align__(16) float g_kp[6 * K];   // akt | bkt | ekc2 | lo | hi | nw

__device__ __forceinline__ float ex2f(float x) {
    float y;
    asm("ex2.approx.ftz.f32 %0, %1;" : "=f"(y) : "f"(x));
    return y;
}
__device__ __forceinline__ unsigned long long packdup(float a) {
    unsigned long long r;
    asm("mov.b64 %0, {%1, %1};" : "=l"(r) : "f"(a));
    return r;
}
__device__ __forceinline__ void unpack2(unsigned long long v, float& lo, float& hi) {
    asm("mov.b64 {%0, %1}, %2;" : "=f"(lo), "=f"(hi) : "l"(v));
}
__device__ __forceinline__ void ffma2(unsigned long long& d,
                                      unsigned long long a,
                                      unsigned long long b) {
    asm("fma.rn.f32x2 %0, %1, %2, %0;" : "+l"(d) : "l"(a), "l"(b));
}

// ---------------------------------------------------------------------------
// Folded per-k constants. dist = base + ak*sv + bk, ak=-2*mean, bk=F*mean^2.
// arg = dist * ekc2 (ekc2 = -log2e/(2 sigma^2) < 0), computed as
// arg = fma(base, ekc2, fma(sx1r, akt, bkt) - sx2c*akt).
// clip(dist,[CMIN,CMAX]) <=> clamp(arg,[CMAX*ekc2, CMIN*ekc2]).
__global__ void params_kernel(const float* __restrict__ sig,
                              const float* __restrict__ mean,
                              const float* __restrict__ sp) {
    if (threadIdx.x == 0) {
        float w[K];
        float m = -3.4e38f;
        #pragma unroll
        for (int k = 0; k < K; k++) {
            float v = 1.0f / (sp[k] * sp[k]);
            w[k] = v;
            if (v > m) m = v;
        }
        float s = 0.0f;
        #pragma unroll
        for (int k = 0; k < K; k++) { w[k] = __expf(w[k] - m); s += w[k]; }
        float inv_s = 1.0f / s;
        #pragma unroll
        for (int k = 0; k < K; k++) {
            float ekc2 = -L2E / (2.0f * sig[k] * sig[k]);
            float ak   = -2.0f * mean[k];
            float bk   = (float)F * mean[k] * mean[k];
            g_kp[k]         = ak * ekc2;      // akt
            g_kp[K + k]     = bk * ekc2;      // bkt
            g_kp[2 * K + k] = ekc2;
            g_kp[3 * K + k] = CMAX * ekc2;    // lo
            g_kp[4 * K + k] = CMIN * ekc2;    // hi
            g_kp[5 * K + k] = w[k] * inv_s;   // normalized weight
        }
    }
}

__global__ void zero_S_kernel() {
    int i = blockIdx.x * blockDim.x + threadIdx.x;
    if (i < K * R) g_S[i] = 0.0f;
}

// Row sums and squared norms of x1 and x2 (one warp per row).
__global__ void stats_kernel(const float* __restrict__ x1,
                             const float* __restrict__ x2) {
    int w = blockIdx.x * (blockDim.x >> 5) + (threadIdx.x >> 5);
    int lane = threadIdx.x & 31;
    if (w >= 2 * R) return;
    const float* x = (w < R) ? x1 : x2;
    int row = (w < R) ? w : (w - R);
    float s = 0.0f, q = 0.0f;
    #pragma unroll
    for (int i = 0; i < F / 32; i++) {
        float v = x[(size_t)row * F + lane + i * 32];
        s += v;
        q = fmaf(v, v, q);
    }
    #pragma unroll
    for (int o = 16; o > 0; o >>= 1) {
        s += __shfl_xor_sync(0xFFFFFFFFu, s, o);
        q += __shfl_xor_sync(0xFFFFFFFFu, q, o);
    }
    if (lane == 0) {
        int off = (w < R) ? 0 : 2 * R;
        g_rs[off + row]     = s;
        g_rs[off + R + row] = q;
    }
}

// ---------------------------------------------------------------------------
// Kernel A: 128x128x16 fp32 GEMM tile, 8x8 microtile with packed f32x2 FFMA;
// epilogue stores base and accumulates S[k,r] via shuffles + atomics.
__global__ void __launch_bounds__(256, 2)
kernelA(const float* __restrict__ x1, const float* __restrict__ x2) {
    __shared__ float As[BK][BM + 4];
    __shared__ float Bs[BK][BN + 4];
    __shared__ float skp[6 * K];

    const int tid = threadIdx.x;
    if (tid < 6 * K) skp[tid] = g_kp[tid];

    const int tx = tid & 15;          // 16 column groups
    const int ty = tid >> 4;          // 16 row groups
    const int r0 = blockIdx.y * BM;
    const int c0 = blockIdx.x * BN;

    // loader: each thread loads 8 consecutive floats (2 float4) of one row
    const int lrow = tid >> 1;        // 0..127
    const int lc8  = (tid & 1) * 8;   // 0 or 8

    unsigned long long acc[8][4];     // acc[i][j2] packs columns (2*j2, 2*j2+1)
    #pragma unroll
    for (int i = 0; i < 8; i++)
        #pragma unroll
        for (int j = 0; j < 4; j++) acc[i][j] = 0ull;

    const float* ap = x1 + (size_t)(r0 + lrow) * F + lc8;
    const float* bp = x2 + (size_t)(c0 + lrow) * F + lc8;

    float4 apre0 = *(const float4*)ap;
    float4 apre1 = *(const float4*)(ap + 4);
    float4 bpre0 = *(const float4*)bp;
    float4 bpre1 = *(const float4*)(bp + 4);

    for (int k0 = 0; k0 < F; k0 += BK) {
        __syncthreads();
        As[lc8 + 0][lrow] = apre0.x; As[lc8 + 1][lrow] = apre0.y;
        As[lc8 + 2][lrow] = apre0.z; As[lc8 + 3][lrow] = apre0.w;
        As[lc8 + 4][lrow] = apre1.x; As[lc8 + 5][lrow] = apre1.y;
        As[lc8 + 6][lrow] = apre1.z; As[lc8 + 7][lrow] = apre1.w;
        Bs[lc8 + 0][lrow] = bpre0.x; Bs[lc8 + 1][lrow] = bpre0.y;
        Bs[lc8 + 2][lrow] = bpre0.z; Bs[lc8 + 3][lrow] = bpre0.w;
        Bs[lc8 + 4][lrow] = bpre1.x; Bs[lc8 + 5][lrow] = bpre1.y;
        Bs[lc8 + 6][lrow] = bpre1.z; Bs[lc8 + 7][lrow] = bpre1.w;
        __syncthreads();
        if (k0 + BK < F) {
            apre0 = *(const float4*)(ap + k0 + BK);
            apre1 = *(const float4*)(ap + k0 + BK + 4);
            bpre0 = *(const float4*)(bp + k0 + BK);
            bpre1 = *(const float4*)(bp + k0 + BK + 4);
        }
        #pragma unroll
        for (int kk = 0; kk < BK; kk++) {
            float4 a0 = *(const float4*)&As[kk][ty * 8];
            float4 a1 = *(const float4*)&As[kk][ty * 8 + 4];
            ulonglong2 b0 = *(const ulonglong2*)&Bs[kk][tx * 8];
            ulonglong2 b1 = *(const ulonglong2*)&Bs[kk][tx * 8 + 4];
            unsigned long long bb[4] = {b0.x, b0.y, b1.x, b1.y};
            float ar[8] = {a0.x, a0.y, a0.z, a0.w, a1.x, a1.y, a1.z, a1.w};
            #pragma unroll
            for (int i = 0; i < 8; i++) {
                unsigned long long ad = packdup(ar[i]);
                #pragma unroll
                for (int j = 0; j < 4; j++) ffma2(acc[i][j], ad, bb[j]);
            }
        }
    }

    // ---- epilogue ----
    const int rbase = r0 + ty * 8;
    const int cbase = c0 + tx * 8;

    // unpack accumulators
    float bacc[8][8];
    #pragma unroll
    for (int i = 0; i < 8; i++)
        #pragma unroll
        for (int j = 0; j < 4; j++)
            unpack2(acc[i][j], bacc[i][2 * j], bacc[i][2 * j + 1]);

    // squared norms -> transform into base, store to g_base
    {
        float4 n21a = *(const float4*)&g_rs[R + rbase];
        float4 n21b = *(const float4*)&g_rs[R + rbase + 4];
        float4 n22a = *(const float4*)&g_rs[3 * R + cbase];
        float4 n22b = *(const float4*)&g_rs[3 * R + cbase + 4];
        float n21[8] = {n21a.x, n21a.y, n21a.z, n21a.w, n21b.x, n21b.y, n21b.z, n21b.w};
        float n22[8] = {n22a.x, n22a.y, n22a.z, n22a.w, n22b.x, n22b.y, n22b.z, n22b.w};
        #pragma unroll
        for (int i = 0; i < 8; i++) {
            #pragma unroll
            for (int j = 0; j < 8; j++)
                bacc[i][j] = n21[i] + n22[j] - 2.0f * bacc[i][j];
            float* dst = &g_base[(size_t)(rbase + i) * R + cbase];
            float4 o0 = {bacc[i][0], bacc[i][1], bacc[i][2], bacc[i][3]};
            float4 o1 = {bacc[i][4], bacc[i][5], bacc[i][6], bacc[i][7]};
            *(float4*)dst = o0;
            *(float4*)(dst + 4) = o1;
        }
    }

    // row/col sums
    float4 s1a = *(const float4*)&g_rs[rbase];
    float4 s1b = *(const float4*)&g_rs[rbase + 4];
    float4 s2a = *(const float4*)&g_rs[2 * R + cbase];
    float4 s2b = *(const float4*)&g_rs[2 * R + cbase + 4];
    float sx1r[8] = {s1a.x, s1a.y, s1a.z, s1a.w, s1b.x, s1b.y, s1b.z, s1b.w};
    float sx2c[8] = {s2a.x, s2a.y, s2a.z, s2a.w, s2b.x, s2b.y, s2b.z, s2b.w};

    #pragma unroll
    for (int k = 0; k < K; k++) {
        const float akt  = skp[k];
        const float bkt  = skp[K + k];
        const float ekc2 = skp[2 * K + k];
        const float lo   = skp[3 * K + k];
        const float hi   = skp[4 * K + k];
        float pi[8], qj[8];
        #pragma unroll
        for (int i = 0; i < 8; i++) pi[i] = fmaf(sx1r[i], akt, bkt);
        #pragma unroll
        for (int j = 0; j < 8; j++) qj[j] = sx2c[j] * akt;

        float ss[8];
        #pragma unroll
        for (int i = 0; i < 8; i++) ss[i] = 0.0f;

        #pragma unroll
        for (int i = 0; i < 8; i++) {
            #pragma unroll
            for (int j = 0; j < 8; j++) {
                float arg = fmaf(bacc[i][j], ekc2, pi[i] - qj[j]);
                arg = fminf(fmaxf(arg, lo), hi);
                float kv = ex2f(arg);            // exp(-dist/(2 sigma^2)) in (0,1]
                ss[i] += ex2f(kv * L2E);         // exp(kv)
            }
        }
        // reduce across the 16 lanes sharing the same rows (xor <= 8 stays
        // within each 16-lane half of the warp)
        #pragma unroll
        for (int i = 0; i < 8; i++) {
            float v = ss[i];
            v += __shfl_xor_sync(0xFFFFFFFFu, v, 1);
            v += __shfl_xor_sync(0xFFFFFFFFu, v, 2);
            v += __shfl_xor_sync(0xFFFFFFFFu, v, 4);
            v += __shfl_xor_sync(0xFFFFFFFFu, v, 8);
            if (tx == 0) atomicAdd(&g_S[k * R + rbase + i], v);
        }
    }
}

// ---------------------------------------------------------------------------
// Kernel B: one block per row r; recompute kv from stored base, normalize,
// weighted sum over k, write output.
__global__ void __launch_bounds__(256)
kernelB(float* __restrict__ out) {
    const int r = blockIdx.x;
    __shared__ float sa[K], se[K], slo[K], shi[K], sw[K], sp_[K];
    if (threadIdx.x < K) {
        int k = threadIdx.x;
        float akt = g_kp[k];
        float bkt = g_kp[K + k];
        float sx1r = g_rs[r];
        sa[k]  = akt;
        se[k]  = g_kp[2 * K + k];
        slo[k] = g_kp[3 * K + k];
        shi[k] = g_kp[4 * K + k];
        sw[k]  = g_kp[5 * K + k] / g_S[k * R + r];
        sp_[k] = fmaf(sx1r, akt, bkt);   // pi for this row
    }
    __syncthreads();

    float akt[K], ekc2[K], lo[K], hi[K], wk[K], pr[K];
    #pragma unroll
    for (int k = 0; k < K; k++) {
        akt[k] = sa[k]; ekc2[k] = se[k]; lo[k] = slo[k];
        hi[k] = shi[k]; wk[k] = sw[k];   pr[k] = sp_[k];
    }
    const float* baserow = g_base + (size_t)r * R;
    float* outrow = out + (size_t)r * R;

    #pragma unroll
    for (int it = 0; it < R / (256 * 4); it++) {
        int c = (it * 256 + threadIdx.x) * 4;
        float4 b4 = *(const float4*)(baserow + c);
        float4 s4 = *(const float4*)(g_rs + 2 * R + c);
        float bb[4] = {b4.x, b4.y, b4.z, b4.w};
        float cc[4] = {s4.x, s4.y, s4.z, s4.w};
        float o[4] = {0.0f, 0.0f, 0.0f, 0.0f};
        #pragma unroll
        for (int j = 0; j < 4; j++) {
            #pragma unroll
            for (int k = 0; k < K; k++) {
                float q = cc[j] * akt[k];
                float arg = fmaf(bb[j], ekc2[k], pr[k] - q);
                arg = fminf(fmaxf(arg, lo[k]), hi[k]);
                float kv = ex2f(arg);
                o[j] = fmaf(ex2f(kv * L2E), wk[k], o[j]);
            }
        }
        float4 ov = {o[0], o[1], o[2], o[3]};
        *(float4*)(outrow + c) = ov;
    }
}

// ---------------------------------------------------------------------------
extern "C" void kernel_launch(void* const* d_in, const int* in_sizes, int n_in,
                              void* d_out, int out_size) {
    const float* x1   = (const float*)d_in[0];  // [R, F]
    const float* x2   = (const float*)d_in[1];  // [R, F]
    const float* sig  = (const float*)d_in[2];  // [K]
    const float* mean = (const float*)d_in[3];  // [K]
    const float* sp   = (const float*)d_in[4];  // [K]
    float* out = (float*)d_out;                 // [R, R]

    params_kernel<<<1, 32>>>(sig, mean, sp);
    zero_S_kernel<<<(K * R + 255) / 256, 256>>>();
    stats_kernel<<<(2 * R) / 8, 256>>>(x1, x2);

    dim3 gridA(R / BN, R / BM);
    kernelA<<<gridA, 256>>>(x1, x2);

    kernelB<<<R, 256>>>(out);
}

// round 8
// speedup vs baseline: 1.8841x; 1.5697x over previous
#include <cuda_runtime.h>
#include <cuda_bf16.h>
#include <cstdint>

#define R 4096
#define F 256
#define K 8
#define CMIN 1e-6f
#define CMAX 1e6f
#define C_BIAS 0.5287663729448977f  /* log2(log2(e)) */

#define BM 128
#define BN 128
#define TILE_B 16384               // one 128row x 128B bf16 tile (BK=64)
#define A_SMEM (4 * TILE_B + 1024)

// Scratch (static device globals — no runtime allocation)
__device__ __align__(16) float g_base[(size_t)R * (size_t)R];  // 64 MB
__device__ __align__(16) float g_S[K * R];
__device__ __align__(16) float g_rs[4 * R];     // sx1 | n2x1 | sx2 | n2x2
__device__ __align__(16) float g_kp[6 * K];     // akt|bkt2|ekc2|lo|hi|nw
__device__ __align__(16) __nv_bfloat16 g_x1h[R * F];
__device__ __align__(16) __nv_bfloat16 g_x1l[R * F];
__device__ __align__(16) __nv_bfloat16 g_x2h[R * F];
__device__ __align__(16) __nv_bfloat16 g_x2l[R * F];

__device__ __forceinline__ uint32_t smem_u32(const void* p) {
    uint32_t a;
    asm("{ .reg .u64 t; cvta.to.shared.u64 t, %1; cvt.u32.u64 %0, t; }"
        : "=r"(a) : "l"(p));
    return a;
}
__device__ __forceinline__ float ex2f(float x) {
    float y;
    asm("ex2.approx.ftz.f32 %0, %1;" : "=f"(y) : "f"(x));
    return y;
}
__device__ __forceinline__ void ldsm_x4(uint32_t* r, uint32_t addr) {
    asm volatile("ldmatrix.sync.aligned.m8n8.x4.shared.b16 {%0,%1,%2,%3}, [%4];"
                 : "=r"(r[0]), "=r"(r[1]), "=r"(r[2]), "=r"(r[3]) : "r"(addr));
}
__device__ __forceinline__ void mma16816(float* c, const uint32_t* a,
                                         uint32_t b0, uint32_t b1) {
    asm volatile(
        "mma.sync.aligned.m16n8k16.row.col.f32.bf16.bf16.f32 "
        "{%0,%1,%2,%3}, {%4,%5,%6,%7}, {%8,%9}, {%0,%1,%2,%3};"
        : "+f"(c[0]), "+f"(c[1]), "+f"(c[2]), "+f"(c[3])
        : "r"(a[0]), "r"(a[1]), "r"(a[2]), "r"(a[3]), "r"(b0), "r"(b1));
}

// ---------------------------------------------------------------------------
// Per-k constants. arg = dist*ekc2 + C_BIAS, ekc2 = -log2e/(2 sigma^2) < 0.
// e^kv = ex2(ex2(arg)). Clamp arg in [CMAX*ekc2+C, CMIN*ekc2+C].
__global__ void params_kernel(const float* __restrict__ sig,
                              const float* __restrict__ mean,
                              const float* __restrict__ sp) {
    if (threadIdx.x == 0) {
        const float L2E = 1.4426950408889634f;
        float w[K];
        float m = -3.4e38f;
        #pragma unroll
        for (int k = 0; k < K; k++) {
            float v = 1.0f / (sp[k] * sp[k]);
            w[k] = v;
            if (v > m) m = v;
        }
        float s = 0.0f;
        #pragma unroll
        for (int k = 0; k < K; k++) { w[k] = __expf(w[k] - m); s += w[k]; }
        float inv_s = 1.0f / s;
        #pragma unroll
        for (int k = 0; k < K; k++) {
            float ekc2 = -L2E / (2.0f * sig[k] * sig[k]);
            float ak   = -2.0f * mean[k];
            float bk   = (float)F * mean[k] * mean[k];
            g_kp[k]         = ak * ekc2;              // akt
            g_kp[K + k]     = bk * ekc2 + C_BIAS;     // bkt2
            g_kp[2 * K + k] = ekc2;
            g_kp[3 * K + k] = CMAX * ekc2 + C_BIAS;   // lo
            g_kp[4 * K + k] = CMIN * ekc2 + C_BIAS;   // hi
            g_kp[5 * K + k] = w[k] * inv_s;           // normalized weight
        }
    }
}

__global__ void zero_S_kernel() {
    int i = blockIdx.x * blockDim.x + threadIdx.x;
    if (i < K * R) g_S[i] = 0.0f;
}

// Split fp32 -> bf16 hi + bf16 lo (x ≈ hi + lo)
__global__ void split_kernel(const float* __restrict__ x1,
                             const float* __restrict__ x2) {
    int i = blockIdx.x * blockDim.x + threadIdx.x;
    if (i >= R * F / 4) return;
    float4 v1 = ((const float4*)x1)[i];
    float4 v2 = ((const float4*)x2)[i];
    const float* a = (const float*)&v1;
    const float* b = (const float*)&v2;
    #pragma unroll
    for (int e = 0; e < 4; e++) {
        __nv_bfloat16 h = __float2bfloat16(a[e]);
        g_x1h[i * 4 + e] = h;
        g_x1l[i * 4 + e] = __float2bfloat16(a[e] - __bfloat162float(h));
        h = __float2bfloat16(b[e]);
        g_x2h[i * 4 + e] = h;
        g_x2l[i * 4 + e] = __float2bfloat16(b[e] - __bfloat162float(h));
    }
}

// Row sums and squared norms of x1 and x2 (one warp per row).
__global__ void stats_kernel(const float* __restrict__ x1,
                             const float* __restrict__ x2) {
    int w = blockIdx.x * (blockDim.x >> 5) + (threadIdx.x >> 5);
    int lane = threadIdx.x & 31;
    if (w >= 2 * R) return;
    const float* x = (w < R) ? x1 : x2;
    int row = (w < R) ? w : (w - R);
    float s = 0.0f, q = 0.0f;
    #pragma unroll
    for (int i = 0; i < F / 32; i++) {
        float v = x[(size_t)row * F + lane + i * 32];
        s += v;
        q = fmaf(v, v, q);
    }
    #pragma unroll
    for (int o = 16; o > 0; o >>= 1) {
        s += __shfl_xor_sync(0xFFFFFFFFu, s, o);
        q += __shfl_xor_sync(0xFFFFFFFFu, q, o);
    }
    if (lane == 0) {
        int off = (w < R) ? 0 : 2 * R;
        g_rs[off + row]     = s;
        g_rs[off + R + row] = q;
    }
}

// ---------------------------------------------------------------------------
// Kernel A: 128x128 tile, bf16 split-GEMM (hh+hl+lh) via mma.sync m16n8k16.
// 8 warps in 2(m) x 4(n) grid, 64x32 per warp, fp32 register accumulators.
// Epilogue: base transform + store + double-exp S accumulation.
__global__ void __launch_bounds__(256, 2)
kernelA() {
    extern __shared__ char dynsmem[];
    __shared__ float skp[6 * K];

    const int tid  = threadIdx.x;
    const int wid  = tid >> 5;
    const int lane = tid & 31;
    const int wm = wid & 1;          // m position (0..1) -> 64 rows
    const int wn = wid >> 1;         // n position (0..3) -> 32 cols
    const int ln15 = lane & 15;
    const int hi16 = lane >> 4;
    const int r0 = blockIdx.y * BM;
    const int c0 = blockIdx.x * BN;

    const uint32_t dsb = smem_u32(dynsmem);
    const uint32_t tiles_u = (dsb + 1023u) & ~1023u;
    char* tiles = dynsmem + (tiles_u - dsb);

    if (tid < 6 * K) skp[tid] = g_kp[tid];

    // loader mapping: 128 rows x 64 bf16 tiles, SW128 swizzle
    const int lrow  = tid >> 1;
    const int lcol0 = (tid & 1) * 32;
    const __nv_bfloat16* pah = g_x1h + (size_t)(r0 + lrow) * F + lcol0;
    const __nv_bfloat16* pal = g_x1l + (size_t)(r0 + lrow) * F + lcol0;
    const __nv_bfloat16* pbh = g_x2h + (size_t)(c0 + lrow) * F + lcol0;
    const __nv_bfloat16* pbl = g_x2l + (size_t)(c0 + lrow) * F + lcol0;

    // ldmatrix base addresses (row part; chunk xor added per k-step)
    const uint32_t a_row = (uint32_t)(wm * 64 + ln15) * 128u;
    const uint32_t b_row = (uint32_t)(wn * 32 + ln15) * 128u;
    const uint32_t ah_base = tiles_u + 0 * TILE_B + a_row;
    const uint32_t al_base = tiles_u + 1 * TILE_B + a_row;
    const uint32_t bh_base = tiles_u + 2 * TILE_B + b_row;
    const uint32_t bl_base = tiles_u + 3 * TILE_B + b_row;

    float acc[4][4][4];
    #pragma unroll
    for (int i = 0; i < 4; i++)
        #pragma unroll
        for (int j = 0; j < 4; j++)
            #pragma unroll
            for (int c = 0; c < 4; c++) acc[i][j][c] = 0.0f;

    for (int kc = 0; kc < 4; kc++) {
        const int k0 = kc * 64;
        __syncthreads();
        #pragma unroll
        for (int j = 0; j < 4; j++) {
            uint32_t boff = lrow * 128 + (lcol0 + j * 8) * 2;
            uint32_t sw = boff ^ ((boff >> 3) & 0x70);
            *(uint4*)(tiles + 0 * TILE_B + sw) = *(const uint4*)(pah + k0 + j * 8);
            *(uint4*)(tiles + 1 * TILE_B + sw) = *(const uint4*)(pal + k0 + j * 8);
            *(uint4*)(tiles + 2 * TILE_B + sw) = *(const uint4*)(pbh + k0 + j * 8);
            *(uint4*)(tiles + 3 * TILE_B + sw) = *(const uint4*)(pbl + k0 + j * 8);
        }
        __syncthreads();

        #pragma unroll
        for (int ks = 0; ks < 4; ks++) {
            const uint32_t q = (uint32_t)(((ks * 2 + hi16) ^ (ln15 & 7)) * 16);
            uint32_t ah[4][4], bh[2][4], bl[2][4];
            #pragma unroll
            for (int mf = 0; mf < 4; mf++)
                ldsm_x4(ah[mf], ah_base + q + mf * 2048);
            #pragma unroll
            for (int n2 = 0; n2 < 2; n2++)
                ldsm_x4(bh[n2], bh_base + q + n2 * 2048);
            #pragma unroll
            for (int n2 = 0; n2 < 2; n2++)
                ldsm_x4(bl[n2], bl_base + q + n2 * 2048);

            // hh
            #pragma unroll
            for (int mf = 0; mf < 4; mf++)
                #pragma unroll
                for (int nf = 0; nf < 4; nf++)
                    mma16816(acc[mf][nf], ah[mf],
                             bh[nf >> 1][nf & 1], bh[nf >> 1][(nf & 1) + 2]);
            // hl
            #pragma unroll
            for (int mf = 0; mf < 4; mf++)
                #pragma unroll
                for (int nf = 0; nf < 4; nf++)
                    mma16816(acc[mf][nf], ah[mf],
                             bl[nf >> 1][nf & 1], bl[nf >> 1][(nf & 1) + 2]);
            // lh (A-lo overwrites A-hi registers)
            #pragma unroll
            for (int mf = 0; mf < 4; mf++)
                ldsm_x4(ah[mf], al_base + q + mf * 2048);
            #pragma unroll
            for (int mf = 0; mf < 4; mf++)
                #pragma unroll
                for (int nf = 0; nf < 4; nf++)
                    mma16816(acc[mf][nf], ah[mf],
                             bh[nf >> 1][nf & 1], bh[nf >> 1][(nf & 1) + 2]);
        }
    }

    // ---- epilogue ----
    // fragment layout: elem (mf, nf, half, e):
    //   row = r0 + wm*64 + mf*16 + half*8 + lane/4
    //   col = c0 + wn*32 + nf*8 + (lane&3)*2 + e
    const int rbase = r0 + wm * 64 + (lane >> 2);
    const int cbase = c0 + wn * 32 + (lane & 3) * 2;

    float sx1r8[8], n21r8[8];
    #pragma unroll
    for (int i = 0; i < 8; i++) {
        int row = rbase + (i >> 1) * 16 + (i & 1) * 8;
        sx1r8[i] = g_rs[row];
        n21r8[i] = g_rs[R + row];
    }
    float n22c[8], s2c[8];
    #pragma unroll
    for (int nf = 0; nf < 4; nf++) {
        float2 n2 = *(const float2*)&g_rs[3 * R + cbase + nf * 8];
        float2 s2 = *(const float2*)&g_rs[2 * R + cbase + nf * 8];
        n22c[nf * 2] = n2.x; n22c[nf * 2 + 1] = n2.y;
        s2c[nf * 2]  = s2.x; s2c[nf * 2 + 1]  = s2.y;
    }

    // transform to base and store
    #pragma unroll
    for (int mf = 0; mf < 4; mf++) {
        #pragma unroll
        for (int h = 0; h < 2; h++) {
            int row = rbase + mf * 16 + h * 8;
            float n21 = n21r8[mf * 2 + h];
            #pragma unroll
            for (int nf = 0; nf < 4; nf++) {
                float b0 = n21 + n22c[nf * 2]     - 2.0f * acc[mf][nf][h * 2];
                float b1 = n21 + n22c[nf * 2 + 1] - 2.0f * acc[mf][nf][h * 2 + 1];
                acc[mf][nf][h * 2]     = b0;
                acc[mf][nf][h * 2 + 1] = b1;
                float2 o = {b0, b1};
                *(float2*)&g_base[(size_t)row * R + cbase + nf * 8] = o;
            }
        }
    }

    // S accumulation: per k, per row-fragment, sum over this thread's 8 cols,
    // quad-reduce (lanes sharing a row), atomic to g_S.
    #pragma unroll
    for (int k = 0; k < K; k++) {
        const float akt  = skp[k];
        const float nakt = -akt;
        const float bkt2 = skp[K + k];
        const float ekc2 = skp[2 * K + k];
        const float lo   = skp[3 * K + k];
        const float hi   = skp[4 * K + k];
        #pragma unroll
        for (int mf = 0; mf < 4; mf++) {
            #pragma unroll
            for (int h = 0; h < 2; h++) {
                const float pi = fmaf(sx1r8[mf * 2 + h], akt, bkt2);
                float s = 0.0f;
                #pragma unroll
                for (int nf = 0; nf < 4; nf++) {
                    #pragma unroll
                    for (int e = 0; e < 2; e++) {
                        float arg = fmaf(acc[mf][nf][h * 2 + e], ekc2,
                                         fmaf(s2c[nf * 2 + e], nakt, pi));
                        arg = fminf(fmaxf(arg, lo), hi);
                        s += ex2f(ex2f(arg));   // = exp(kv)
                    }
                }
                s += __shfl_xor_sync(0xFFFFFFFFu, s, 1);
                s += __shfl_xor_sync(0xFFFFFFFFu, s, 2);
                if ((lane & 3) == 0)
                    atomicAdd(&g_S[k * R + rbase + mf * 16 + h * 8], s);
            }
        }
    }
}

// ---------------------------------------------------------------------------
// Kernel B: one block per row r; recompute numerators from stored base,
// normalize by S, weighted sum over k.
__global__ void __launch_bounds__(256)
kernelB(float* __restrict__ out) {
    const int r = blockIdx.x;
    __shared__ float sa[K], se[K], slo[K], shi[K], sw[K], sp_[K];
    if (threadIdx.x < K) {
        int k = threadIdx.x;
        float akt = g_kp[k];
        sa[k]  = akt;
        se[k]  = g_kp[2 * K + k];
        slo[k] = g_kp[3 * K + k];
        shi[k] = g_kp[4 * K + k];
        sw[k]  = g_kp[5 * K + k] / g_S[k * R + r];
        sp_[k] = fmaf(g_rs[r], akt, g_kp[K + k]);
    }
    __syncthreads();

    float nakt[K], ekc2[K], lo[K], hi[K], wk[K], pr[K];
    #pragma unroll
    for (int k = 0; k < K; k++) {
        nakt[k] = -sa[k]; ekc2[k] = se[k]; lo[k] = slo[k];
        hi[k] = shi[k];   wk[k] = sw[k];   pr[k] = sp_[k];
    }
    const float* baserow = g_base + (size_t)r * R;
    float* outrow = out + (size_t)r * R;

    #pragma unroll
    for (int it = 0; it < R / (256 * 4); it++) {
        int c = (it * 256 + threadIdx.x) * 4;
        float4 b4 = *(const float4*)(baserow + c);
        float4 s4 = *(const float4*)(g_rs + 2 * R + c);
        const float* bb = (const float*)&b4;
        const float* cc = (const float*)&s4;
        float o[4] = {0.0f, 0.0f, 0.0f, 0.0f};
        #pragma unroll
        for (int j = 0; j < 4; j++) {
            #pragma unroll
            for (int k = 0; k < K; k++) {
                float arg = fmaf(bb[j], ekc2[k], fmaf(cc[j], nakt[k], pr[k]));
                arg = fminf(fmaxf(arg, lo[k]), hi[k]);
                o[j] = fmaf(ex2f(ex2f(arg)), wk[k], o[j]);
            }
        }
        float4 ov = {o[0], o[1], o[2], o[3]};
        *(float4*)(outrow + c) = ov;
    }
}

// ---------------------------------------------------------------------------
extern "C" void kernel_launch(void* const* d_in, const int* in_sizes, int n_in,
                              void* d_out, int out_size) {
    const float* x1   = (const float*)d_in[0];  // [R, F]
    const float* x2   = (const float*)d_in[1];  // [R, F]
    const float* sig  = (const float*)d_in[2];  // [K]
    const float* mean = (const float*)d_in[3];  // [K]
    const float* sp   = (const float*)d_in[4];  // [K]
    float* out = (float*)d_out;                 // [R, R]

    cudaFuncSetAttribute(kernelA, cudaFuncAttributeMaxDynamicSharedMemorySize,
                         A_SMEM);

    params_kernel<<<1, 32>>>(sig, mean, sp);
    zero_S_kernel<<<(K * R + 255) / 256, 256>>>();
    stats_kernel<<<(2 * R) / 8, 256>>>(x1, x2);
    split_kernel<<<(R * F / 4 + 255) / 256, 256>>>(x1, x2);

    dim3 gridA(R / BN, R / BM);
    kernelA<<<gridA, 256, A_SMEM>>>();

    kernelB<<<R, 256>>>(out);
}